// round 12
// baseline (speedup 1.0000x reference)
#include <cuda_runtime.h>
#include <cuda_bf16.h>
#include <math.h>

#define B_   4
#define S_   8192
#define D_   128
#define H_   8
#define SP_  1024
#define BH_  (B_*H_)
#define NROWS (B_*S_)      // 32768
#define MAXC 64
#define OUT_ELEMS  (B_*S_*D_)
#define ATTN_ELEMS (BH_*SP_*SP_)

#define TILE_M 64
#define GEMM_BLOCKS (NROWS / TILE_M)   // 512

// smem (bf16, padded row stride 136 -> conflict-free fragment loads)
#define APAD 136
#define A_TILE_ELEMS (TILE_M * APAD)   // 8704
#define B_TILE_ELEMS (128 * APAD)      // 17408
#define SMEM_BYTES ((2*A_TILE_ELEMS + 2*B_TILE_ELEMS) * 2)   // 104448 B

// Scratch (device globals)
__device__ float g_Ublend[NROWS*D_];   // blended v rows (rare multi-cand rows)
__device__ float g_rareP[NROWS*MAXC];  // softmax probs for rare rows
__device__ __nv_bfloat16 g_W2h[D_*D_]; // bf16 hi of (Wv@Wo), TRANSPOSED [n][k]
__device__ __nv_bfloat16 g_W2l[D_*D_]; // bf16 lo residual,   TRANSPOSED [n][k]
__device__ float g_b2[D_];             // bv @ Wo + bo
__device__ int   g_candK[SP_*MAXC];
__device__ int   g_candCnt[SP_];

// row s in (B, S) order -> row in (B, H, Sp) order
__device__ __forceinline__ int split_row(int s) {
    int b = s >> 13;
    int r = s & 8191;
    return (((b << 3) | (r & 7)) << 10) | (r >> 3);
}

__device__ __forceinline__ void mma_bf16(
    float& c0, float& c1, float& c2, float& c3,
    unsigned a0, unsigned a1, unsigned a2, unsigned a3,
    unsigned b0, unsigned b1)
{
    asm volatile(
        "mma.sync.aligned.m16n8k16.row.col.f32.bf16.bf16.f32 "
        "{%0,%1,%2,%3},{%4,%5,%6,%7},{%8,%9},{%0,%1,%2,%3};"
        : "+f"(c0), "+f"(c1), "+f"(c2), "+f"(c3)
        : "r"(a0), "r"(a1), "r"(a2), "r"(a3), "r"(b0), "r"(b1));
}

// ---------------------------------------------------------------------------
// Mask row analysis, warp-per-row (lane bitmask + warp prefix scan).
// ---------------------------------------------------------------------------
__global__ __launch_bounds__(256) void mask_cand(const float* __restrict__ mask)
{
    const int warp = threadIdx.x >> 5;
    const int lane = threadIdx.x & 31;
    const int q    = blockIdx.x * 8 + warp;

    const float4* row4 = (const float4*)(mask + (size_t)q * SP_);
    float v[32];
    float m = -3.4e38f;
#pragma unroll
    for (int j = 0; j < 8; j++) {
        float4 t = row4[j*32 + lane];
        v[j*4+0] = t.x * (-1e9f);
        v[j*4+1] = t.y * (-1e9f);
        v[j*4+2] = t.z * (-1e9f);
        v[j*4+3] = t.w * (-1e9f);
        m = fmaxf(m, fmaxf(fmaxf(v[j*4+0], v[j*4+1]),
                           fmaxf(v[j*4+2], v[j*4+3])));
    }
#pragma unroll
    for (int o = 16; o > 0; o >>= 1)
        m = fmaxf(m, __shfl_xor_sync(0xffffffffu, m, o));
    const float thr = m - 300.0f;

    unsigned int flags = 0;
#pragma unroll
    for (int b = 0; b < 32; b++)
        if (v[b] >= thr) flags |= 1u << b;

    const int cnt = __popc(flags);
    int x = cnt;
#pragma unroll
    for (int o = 1; o < 32; o <<= 1) {
        int y = __shfl_up_sync(0xffffffffu, x, o);
        if (lane >= o) x += y;
    }
    const int excl = x - cnt;
    const int tot  = __shfl_sync(0xffffffffu, x, 31);

    int pos = excl;
    unsigned int f = flags;
    while (f) {
        int b = __ffs(f) - 1;
        f &= f - 1;
        if (pos < MAXC) {
            int j = b >> 2, c = b & 3;
            g_candK[q*MAXC + pos] = (j*32 + lane)*4 + c;
        }
        pos++;
    }
    if (lane == 0) g_candCnt[q] = (tot < MAXC) ? tot : MAXC;
}

// ---------------------------------------------------------------------------
// fused_prep: blocks 0..63 -> W2 (bf16 hi/lo, transposed); block 64 -> b2;
// blocks 65..1088 -> rare-row attention (early exit).
// ---------------------------------------------------------------------------
__global__ __launch_bounds__(256) void fused_prep(
    const float* __restrict__ Wv, const float* __restrict__ Wo,
    const float* __restrict__ bv, const float* __restrict__ bo,
    const float* __restrict__ qin, const float* __restrict__ kin,
    const float* __restrict__ vin, const float* __restrict__ mask,
    const float* __restrict__ Wq, const float* __restrict__ bq,
    const float* __restrict__ Wk, const float* __restrict__ bk)
{
    if (blockIdx.x < 64) {
        const int idx = blockIdx.x * 256 + threadIdx.x;
        const int r = idx >> 7;       // k-dim of final gemm
        const int c = idx & 127;      // n-dim
        const float* wr = Wv + (size_t)r * D_;
        const float* wc = Wo + c;
        float a[16];
#pragma unroll
        for (int u = 0; u < 16; u++) a[u] = 0.f;
        for (int k0 = 0; k0 < D_; k0 += 16) {
#pragma unroll
            for (int u = 0; u < 16; u++)
                a[u] = fmaf(wr[k0+u], wc[(size_t)(k0+u) * D_], a[u]);
        }
        float s = 0.f;
#pragma unroll
        for (int u = 0; u < 16; u++) s += a[u];
        __nv_bfloat16 h = __float2bfloat16(s);
        __nv_bfloat16 l = __float2bfloat16(s - __bfloat162float(h));
        g_W2h[c * D_ + r] = h;      // transposed [n][k]
        g_W2l[c * D_ + r] = l;
        return;
    }
    if (blockIdx.x == 64) {
        const int c = threadIdx.x;
        if (c >= D_) return;
        const float* wc = Wo + c;
        float a[16];
#pragma unroll
        for (int u = 0; u < 16; u++) a[u] = 0.f;
        for (int k0 = 0; k0 < D_; k0 += 16) {
#pragma unroll
            for (int u = 0; u < 16; u++)
                a[u] = fmaf(bv[k0+u], wc[(size_t)(k0+u) * D_], a[u]);
        }
        float s = 0.f;
#pragma unroll
        for (int u = 0; u < 16; u++) s += a[u];
        g_b2[c] = s + bo[c];
        return;
    }

    // ---- rare rows ----
    const int q = blockIdx.x - 65;
    const int cnt = g_candCnt[q];
    if (cnt < 2) return;

    __shared__ float sx[8][MAXC];
    const int w    = threadIdx.x >> 5;
    const int lane = threadIdx.x & 31;

    for (int bh = w * 4; bh < w * 4 + 4; bh++) {
        const int b = bh >> 3;
        const int h = bh & 7;
        const int bhrow = bh * SP_ + q;

        const float* qrow = qin + (size_t)(b * S_ + q * H_ + h) * D_;
        float4 qv = *(const float4*)(qrow + lane*4);
        float qp[4] = { bq[lane*4+0], bq[lane*4+1], bq[lane*4+2], bq[lane*4+3] };
        for (int kk0 = 0; kk0 < D_; kk0 += 4) {
            const int src = kk0 >> 2;
            float c0 = __shfl_sync(0xffffffffu, qv.x, src);
            float c1 = __shfl_sync(0xffffffffu, qv.y, src);
            float c2 = __shfl_sync(0xffffffffu, qv.z, src);
            float c3 = __shfl_sync(0xffffffffu, qv.w, src);
            const float* wp = Wq + (size_t)kk0 * D_ + lane*4;
            float4 w0 = *(const float4*)(wp);
            float4 w1 = *(const float4*)(wp + D_);
            float4 w2 = *(const float4*)(wp + 2*D_);
            float4 w3 = *(const float4*)(wp + 3*D_);
            qp[0] = fmaf(c0,w0.x,fmaf(c1,w1.x,fmaf(c2,w2.x,fmaf(c3,w3.x,qp[0]))));
            qp[1] = fmaf(c0,w0.y,fmaf(c1,w1.y,fmaf(c2,w2.y,fmaf(c3,w3.y,qp[1]))));
            qp[2] = fmaf(c0,w0.z,fmaf(c1,w1.z,fmaf(c2,w2.z,fmaf(c3,w3.z,qp[2]))));
            qp[3] = fmaf(c0,w0.w,fmaf(c1,w1.w,fmaf(c2,w2.w,fmaf(c3,w3.w,qp[3]))));
        }

        float m = -3.4e38f;
        for (int j = 0; j < cnt; j++) {
            const int k = g_candK[q*MAXC + j];
            const float* krow = kin + (size_t)(b * S_ + k * H_ + h) * D_;
            float4 kv = *(const float4*)(krow + lane*4);
            float kp[4] = { bk[lane*4+0], bk[lane*4+1], bk[lane*4+2], bk[lane*4+3] };
            for (int kk0 = 0; kk0 < D_; kk0 += 4) {
                const int src = kk0 >> 2;
                float c0 = __shfl_sync(0xffffffffu, kv.x, src);
                float c1 = __shfl_sync(0xffffffffu, kv.y, src);
                float c2 = __shfl_sync(0xffffffffu, kv.z, src);
                float c3 = __shfl_sync(0xffffffffu, kv.w, src);
                const float* wp = Wk + (size_t)kk0 * D_ + lane*4;
                float4 w0 = *(const float4*)(wp);
                float4 w1 = *(const float4*)(wp + D_);
                float4 w2 = *(const float4*)(wp + 2*D_);
                float4 w3 = *(const float4*)(wp + 3*D_);
                kp[0] = fmaf(c0,w0.x,fmaf(c1,w1.x,fmaf(c2,w2.x,fmaf(c3,w3.x,kp[0]))));
                kp[1] = fmaf(c0,w0.y,fmaf(c1,w1.y,fmaf(c2,w2.y,fmaf(c3,w3.y,kp[1]))));
                kp[2] = fmaf(c0,w0.z,fmaf(c1,w1.z,fmaf(c2,w2.z,fmaf(c3,w3.z,kp[2]))));
                kp[3] = fmaf(c0,w0.w,fmaf(c1,w1.w,fmaf(c2,w2.w,fmaf(c3,w3.w,kp[3]))));
            }
            float d = qp[0]*kp[0] + qp[1]*kp[1] + qp[2]*kp[2] + qp[3]*kp[3];
#pragma unroll
            for (int o = 16; o > 0; o >>= 1)
                d += __shfl_xor_sync(0xffffffffu, d, o);
            float xv = d / 11.313708498984761f + mask[(size_t)q*SP_ + k] * (-1e9f);
            if (lane == 0) sx[w][j] = xv;
            m = fmaxf(m, xv);
        }
        __syncwarp();

        float sum = 0.f;
        for (int j = 0; j < cnt; j++) sum += expf(sx[w][j] - m);
        const float inv = 1.0f / sum;

        float4 u = make_float4(0.f, 0.f, 0.f, 0.f);
        for (int j = 0; j < cnt; j++) {
            const int k = g_candK[q*MAXC + j];
            const float p = expf(sx[w][j] - m) * inv;
            const float* vrow = vin + (size_t)(b * S_ + k * H_ + h) * D_;
            float4 vr = *(const float4*)(vrow + lane*4);
            u.x = fmaf(p, vr.x, u.x);
            u.y = fmaf(p, vr.y, u.y);
            u.z = fmaf(p, vr.z, u.z);
            u.w = fmaf(p, vr.w, u.w);
            if (lane == 0) g_rareP[(size_t)bhrow * MAXC + j] = p;
        }
        *(float4*)(g_Ublend + (size_t)bhrow * D_ + lane*4) = u;
        __syncwarp();
    }
}

// ---------------------------------------------------------------------------
// Attention output writer: one warp per bh-row (streaming stores).
// ---------------------------------------------------------------------------
__global__ __launch_bounds__(256) void attn_write(float* __restrict__ attnOut)
{
    const int gw   = (blockIdx.x * 256 + threadIdx.x) >> 5;  // 0..32767
    const int lane = threadIdx.x & 31;
    const int qq   = gw & 1023;
    const int cnt  = g_candCnt[qq];
    float4* row = (float4*)(attnOut + (size_t)gw * SP_);

    if (cnt == 1) {
        const int k  = g_candK[qq * MAXC];
        const int kf = k >> 2;
        const int kc = k & 3;
#pragma unroll
        for (int j = 0; j < 8; j++) {
            const int f = j * 32 + lane;
            float4 val = make_float4(0.f, 0.f, 0.f, 0.f);
            if (f == kf) ((float*)&val)[kc] = 1.0f;
            __stcs(&row[f], val);
        }
    } else {
        const float4 z = make_float4(0.f, 0.f, 0.f, 0.f);
#pragma unroll
        for (int j = 0; j < 8; j++)
            __stcs(&row[j * 32 + lane], z);
        __syncwarp();
        if (lane == 0) {
            for (int j = 0; j < cnt; j++)
                attnOut[(size_t)gw * SP_ + g_candK[qq*MAXC + j]] =
                    g_rareP[(size_t)gw * MAXC + j];
        }
    }
}

// ---------------------------------------------------------------------------
// Tensor-core GEMM (bf16x3 split, fp32 accum), occupancy-tuned:
//   64-row tile per block (512 blocks, ~102KB smem -> 2 blocks/SM, 16 warps).
//   Warp w: m16 strip (w>>1), n-half (w&1)*8 n8-tiles -> 32 accum regs.
// Fragment indexing identical to the R11-validated version.
// ---------------------------------------------------------------------------
__global__ __launch_bounds__(256, 2) void gemm_mma(
    const float* __restrict__ A, float* __restrict__ C)
{
    extern __shared__ __align__(16) unsigned char smem_raw[];
    __nv_bfloat16* Ah = (__nv_bfloat16*)smem_raw;
    __nv_bfloat16* Al = Ah + A_TILE_ELEMS;
    __nv_bfloat16* Bh = Al + A_TILE_ELEMS;
    __nv_bfloat16* Bl = Bh + B_TILE_ELEMS;

    const int t    = threadIdx.x;
    const int row0 = blockIdx.x * TILE_M;
    const int warp = t >> 5;
    const int lane = t & 31;

    // ---- stage B (bf16 hi/lo, transposed [n][k]) into padded smem ----
    {
        const int n    = t >> 1;
        const int half = (t & 1) * 64;
        const uint4* srcH = (const uint4*)(g_W2h + n * D_ + half);
        const uint4* srcL = (const uint4*)(g_W2l + n * D_ + half);
        uint4* dstH = (uint4*)(Bh + n * APAD + half);
        uint4* dstL = (uint4*)(Bl + n * APAD + half);
#pragma unroll
        for (int i = 0; i < 8; i++) { dstH[i] = srcH[i]; dstL[i] = srcL[i]; }
    }

    // ---- gather + convert A tile (64 rows) to bf16 hi/lo ----
    {
        const int lrow = t >> 2;             // 0..63
        const int koff = (t & 3) * 32;       // 32 elems per thread
        const int s_in  = row0 + lrow;
        const int bhrow = split_row(s_in);
        const int qq    = bhrow & 1023;
        const int cnt   = g_candCnt[qq];
        const float* arow;
        if (cnt == 1) {
            const int bh = bhrow >> 10;
            const int k  = g_candK[qq * MAXC];
            arow = A + (size_t)((bh >> 3) * S_ + k * H_ + (bh & 7)) * D_;
        } else {
            arow = g_Ublend + (size_t)bhrow * D_;
        }
        const float4* src = (const float4*)(arow + koff);
        __nv_bfloat162* dH = (__nv_bfloat162*)(Ah + lrow * APAD + koff);
        __nv_bfloat162* dL = (__nv_bfloat162*)(Al + lrow * APAD + koff);
#pragma unroll
        for (int i = 0; i < 8; i++) {
            float4 f = src[i];
            __nv_bfloat162 h0 = __float22bfloat162_rn(make_float2(f.x, f.y));
            __nv_bfloat162 h1 = __float22bfloat162_rn(make_float2(f.z, f.w));
            float2 hf0 = __bfloat1622float2(h0);
            float2 hf1 = __bfloat1622float2(h1);
            __nv_bfloat162 l0 = __float22bfloat162_rn(
                make_float2(f.x - hf0.x, f.y - hf0.y));
            __nv_bfloat162 l1 = __float22bfloat162_rn(
                make_float2(f.z - hf1.x, f.w - hf1.y));
            dH[2*i]   = h0; dH[2*i+1] = h1;
            dL[2*i]   = l0; dL[2*i+1] = l1;
        }
    }
    __syncthreads();

    // ---- mma mainloop ----
    const int strip  = (warp >> 1) * 16;    // m strip within 64-row tile
    const int ntBase = (warp & 1) * 8;      // n8-tile half
    const int arow_f = strip + (lane >> 2);
    const int kfrag  = (lane & 3) * 2;
    const int nfrag  = lane >> 2;
    const int cfrag  = (lane & 3) * 2;

    float acc[8][4];
#pragma unroll
    for (int i = 0; i < 8; i++)
#pragma unroll
        for (int j = 0; j < 4; j++) acc[i][j] = 0.f;

#pragma unroll
    for (int ks = 0; ks < 8; ks++) {
        const int K0 = ks * 16;
        const __nv_bfloat16* pa = Ah + arow_f * APAD + K0 + kfrag;
        const __nv_bfloat16* pl = Al + arow_f * APAD + K0 + kfrag;
        unsigned ah0 = *(const unsigned*)(pa);
        unsigned ah1 = *(const unsigned*)(pa + 8*APAD);
        unsigned ah2 = *(const unsigned*)(pa + 8);
        unsigned ah3 = *(const unsigned*)(pa + 8*APAD + 8);
        unsigned al0 = *(const unsigned*)(pl);
        unsigned al1 = *(const unsigned*)(pl + 8*APAD);
        unsigned al2 = *(const unsigned*)(pl + 8);
        unsigned al3 = *(const unsigned*)(pl + 8*APAD + 8);

#pragma unroll
        for (int nt = 0; nt < 8; nt++) {
            const int n8 = ntBase + nt;
            const __nv_bfloat16* pbh = Bh + (n8*8 + nfrag) * APAD + K0 + kfrag;
            const __nv_bfloat16* pbl = Bl + (n8*8 + nfrag) * APAD + K0 + kfrag;
            unsigned bh0 = *(const unsigned*)(pbh);
            unsigned bh1 = *(const unsigned*)(pbh + 8);
            unsigned bl0 = *(const unsigned*)(pbl);
            unsigned bl1 = *(const unsigned*)(pbl + 8);
            mma_bf16(acc[nt][0], acc[nt][1], acc[nt][2], acc[nt][3],
                     ah0, ah1, ah2, ah3, bh0, bh1);
            mma_bf16(acc[nt][0], acc[nt][1], acc[nt][2], acc[nt][3],
                     ah0, ah1, ah2, ah3, bl0, bl1);
            mma_bf16(acc[nt][0], acc[nt][1], acc[nt][2], acc[nt][3],
                     al0, al1, al2, al3, bh0, bh1);
        }
    }

    // ---- epilogue: add bias, store ----
    const int row_g = row0 + strip + (lane >> 2);
#pragma unroll
    for (int nt = 0; nt < 8; nt++) {
        const int col = (ntBase + nt)*8 + cfrag;
        const float2 bb = *(const float2*)&g_b2[col];
        float2 o0 = make_float2(acc[nt][0] + bb.x, acc[nt][1] + bb.y);
        float2 o1 = make_float2(acc[nt][2] + bb.x, acc[nt][3] + bb.y);
        *(float2*)&C[(size_t)row_g * D_ + col]       = o0;
        *(float2*)&C[(size_t)(row_g + 8) * D_ + col] = o1;
    }
}

// ---------------------------------------------------------------------------
extern "C" void kernel_launch(void* const* d_in, const int* in_sizes, int n_in,
                              void* d_out, int out_size)
{
    const float* v    = (const float*)d_in[0];
    const float* k    = (const float*)d_in[1];
    const float* q    = (const float*)d_in[2];
    const float* mask = (const float*)d_in[3];
    const float* Wq   = (const float*)d_in[4];
    const float* bq   = (const float*)d_in[5];
    const float* Wk   = (const float*)d_in[6];
    const float* bk   = (const float*)d_in[7];
    const float* Wv   = (const float*)d_in[8];
    const float* bv   = (const float*)d_in[9];
    const float* Wo   = (const float*)d_in[10];
    const float* bo   = (const float*)d_in[11];
    float* out = (float*)d_out;

    const int hasAttn = (out_size >= OUT_ELEMS + ATTN_ELEMS) ? 1 : 0;
    float* attnOut = hasAttn ? (out + OUT_ELEMS) : nullptr;

    cudaFuncSetAttribute(gemm_mma,
                         cudaFuncAttributeMaxDynamicSharedMemorySize,
                         SMEM_BYTES);

    // 1. Candidate sets per mask row
    mask_cand<<<SP_ / 8, 256>>>(mask);

    // 2. W2 hi/lo + b2 prep + rare-row attention
    fused_prep<<<65 + SP_, 256>>>(Wv, Wo, bv, bo, q, k, v, mask,
                                  Wq, bq, Wk, bk);

    // 3. Attention output (store-bound, near HBM write floor)
    if (hasAttn) attn_write<<<NROWS / 8, 256>>>(attnOut);

    // 4. out = gather(v) @ W2 + b2  (tensor cores, bf16x3, 2 blocks/SM)
    gemm_mma<<<GEMM_BLOCKS, 256, SMEM_BYTES>>>(v, out);
}